// round 3
// baseline (speedup 1.0000x reference)
#include <cuda_runtime.h>

// out = y where 0 < y <= 1 else 0, y = x * w[col] + b[col]
// x: [8192, 4096] f32, w/b: [4096] f32. Pure HBM-bound elementwise.
// R3: persistent grid-stride (888 blocks = 148 SM x 6), w/b staged in smem,
//     4 front-batched LDG.128 per iteration.

#define D_VEC 1024            // 4096 / 4, power of two
#define ITEMS 4
#define THREADS 256
#define BLOCKS 888            // 148 SMs x 6 resident blocks
#define N_VEC (8192 * 1024)   // total float4s = 8388608

__global__ void __launch_bounds__(THREADS)
gegate_kernel(const float4* __restrict__ x,
              const float4* __restrict__ w,
              const float4* __restrict__ b,
              float4* __restrict__ out)
{
    __shared__ float4 sw[D_VEC];
    __shared__ float4 sb[D_VEC];

    // Stage w/b once per block (1024 float4 each, 256 threads x 4)
    #pragma unroll
    for (int i = 0; i < D_VEC / THREADS; i++) {
        int c = threadIdx.x + i * THREADS;
        sw[c] = w[c];
        sb[c] = b[c];
    }
    __syncthreads();

    const int chunk  = THREADS * ITEMS;          // 1024 float4 per block-iter
    const int stride = BLOCKS * chunk;

    // N_VEC = 8388608 = 8192 chunks; 8192 / 888 = 9.22 -> ragged, guard per chunk.
    for (int base = blockIdx.x * chunk + threadIdx.x; base < N_VEC;
         base += stride) {
        // chunk start is always a multiple of 1024, and N_VEC is a multiple of
        // chunk, so if base (first item) is in range the whole chunk is.
        float4 xv[ITEMS];
        #pragma unroll
        for (int i = 0; i < ITEMS; i++)
            xv[i] = __ldcs(&x[base + i * THREADS]);

        #pragma unroll
        for (int i = 0; i < ITEMS; i++) {
            int idx = base + i * THREADS;
            int col = idx & (D_VEC - 1);
            float4 wv = sw[col];
            float4 bv = sb[col];
            float4 y;
            y.x = fmaf(xv[i].x, wv.x, bv.x);
            y.y = fmaf(xv[i].y, wv.y, bv.y);
            y.z = fmaf(xv[i].z, wv.z, bv.z);
            y.w = fmaf(xv[i].w, wv.w, bv.w);
            y.x = (y.x > 0.0f && y.x <= 1.0f) ? y.x : 0.0f;
            y.y = (y.y > 0.0f && y.y <= 1.0f) ? y.y : 0.0f;
            y.z = (y.z > 0.0f && y.z <= 1.0f) ? y.z : 0.0f;
            y.w = (y.w > 0.0f && y.w <= 1.0f) ? y.w : 0.0f;
            __stcs(&out[idx], y);
        }
    }
}

extern "C" void kernel_launch(void* const* d_in, const int* in_sizes, int n_in,
                              void* d_out, int out_size)
{
    const float4* x = (const float4*)d_in[0];
    const float4* w = (const float4*)d_in[1];
    const float4* b = (const float4*)d_in[2];
    float4* out = (float4*)d_out;

    gegate_kernel<<<BLOCKS, THREADS>>>(x, w, b, out);
}

// round 4
// speedup vs baseline: 1.2280x; 1.2280x over previous
#include <cuda_runtime.h>

// out = y where 0 < y <= 1 else 0, y = x * w[col] + b[col]
// x: [8192, 4096] f32, w/b: [4096] f32. Pure HBM-bound elementwise.
// R4: flat grid (no persistence, no smem), 8 float4/thread.
//     Phase 1: 8 front-batched streaming LDG.128 (long same-direction read run)
//     Phase 2: 4 w + 4 b register-cached loads (col pattern has period 4)
//     Phase 3: compute, then 8 grouped STG.128 (long write run).

#define D_VEC 1024            // 4096/4
#define ITEMS 8
#define THREADS 256
#define CHUNK (THREADS * ITEMS)   // 2048 float4 per block (multiple of D_VEC*2)

__global__ void __launch_bounds__(THREADS)
gegate_kernel(const float4* __restrict__ x,
              const float4* __restrict__ w,
              const float4* __restrict__ b,
              float4* __restrict__ out)
{
    const int t = threadIdx.x;
    const int base = blockIdx.x * CHUNK + t;
    // base & 1023 == t  (CHUNK is a multiple of 1024, t < 256)
    // col(i) = (t + i*256) & 1023  -> period 4 in i: {t, t+256, t+512, t+768}

    // Phase 1: batch all x reads (streaming, no L2 retention)
    float4 xv[ITEMS];
    #pragma unroll
    for (int i = 0; i < ITEMS; i++)
        xv[i] = __ldcs(&x[base + i * THREADS]);

    // Phase 2: 4 distinct w/b columns, register-resident
    float4 wv[4], bv[4];
    #pragma unroll
    for (int j = 0; j < 4; j++) {
        wv[j] = __ldg(&w[t + j * THREADS]);
        bv[j] = __ldg(&b[t + j * THREADS]);
    }

    // Phase 3: compute in place
    #pragma unroll
    for (int i = 0; i < ITEMS; i++) {
        const int j = i & 3;
        float4 y;
        y.x = fmaf(xv[i].x, wv[j].x, bv[j].x);
        y.y = fmaf(xv[i].y, wv[j].y, bv[j].y);
        y.z = fmaf(xv[i].z, wv[j].z, bv[j].z);
        y.w = fmaf(xv[i].w, wv[j].w, bv[j].w);
        y.x = (y.x > 0.0f && y.x <= 1.0f) ? y.x : 0.0f;
        y.y = (y.y > 0.0f && y.y <= 1.0f) ? y.y : 0.0f;
        y.z = (y.z > 0.0f && y.z <= 1.0f) ? y.z : 0.0f;
        y.w = (y.w > 0.0f && y.w <= 1.0f) ? y.w : 0.0f;
        xv[i] = y;
    }

    // Phase 4: batch all stores (long write run for the memory controller)
    #pragma unroll
    for (int i = 0; i < ITEMS; i++)
        __stcs(&out[base + i * THREADS], xv[i]);
}

extern "C" void kernel_launch(void* const* d_in, const int* in_sizes, int n_in,
                              void* d_out, int out_size)
{
    const float4* x = (const float4*)d_in[0];
    const float4* w = (const float4*)d_in[1];
    const float4* b = (const float4*)d_in[2];
    float4* out = (float4*)d_out;

    int n_vec = out_size / 4;             // 8388608
    int blocks = n_vec / CHUNK;           // 4096 exactly

    gegate_kernel<<<blocks, THREADS>>>(x, w, b, out);
}